// round 1
// baseline (speedup 1.0000x reference)
#include <cuda_runtime.h>
#include <math.h>

// Problem constants (match reference)
#define NUM_BODY 30
#define NPRED    32   // 30 body + 2 empty
#define NFORM    2
#define KTOP     3
#define SIGMA    0.1f
#define TEMP     0.07f
#define TOL      0.02f

__global__ __launch_bounds__(128)
void logic_model_kernel(const float* __restrict__ t,        // (B,1)
                        const float* __restrict__ ds,       // (B,30)
                        const float* __restrict__ pi,       // (3,)
                        const float* __restrict__ A,        // (2,32)
                        const float* __restrict__ base_p,   // (1,)
                        const float* __restrict__ fw,       // (2,)
                        const float* __restrict__ prob,     // (4,)
                        float* __restrict__ out,            // (B,3)
                        int n)
{
    __shared__ float sA[NFORM][NPRED];
    __shared__ float sPv[NFORM][3];      // pair validity
    __shared__ int   sPc[NFORM][3];      // pair first col (clamped)
    __shared__ int   sQc[NFORM][3];      // pair second col (clamped)

    const int tid = threadIdx.x;

    // Stage A into shared
    if (tid < NFORM * NPRED) {
        sA[tid / NPRED][tid % NPRED] = A[tid];
    }
    __syncthreads();

    // Threads 0 and 1: per-formula top-3 (desc by value, first-index tie break
    // == jax.lax.top_k), then sort indices ascending, build pair tables.
    if (tid < NFORM) {
        int  sel[KTOP];
        bool used[NPRED];
        #pragma unroll
        for (int j = 0; j < NPRED; ++j) used[j] = false;
        #pragma unroll
        for (int k = 0; k < KTOP; ++k) {
            int best = 0;
            float bv = -1e30f;
            #pragma unroll
            for (int j = 0; j < NPRED; ++j) {
                float v = sA[tid][j];
                if (!used[j] && v > bv) { bv = v; best = j; }
            }
            used[best] = true;
            sel[k] = best;
        }
        // sort 3 indices ascending
        #pragma unroll
        for (int a = 0; a < KTOP - 1; ++a)
            #pragma unroll
            for (int b2 = 0; b2 < KTOP - 1 - a; ++b2)
                if (sel[b2] > sel[b2 + 1]) { int tmp = sel[b2]; sel[b2] = sel[b2+1]; sel[b2+1] = tmp; }

        const int pa[3] = {0, 0, 1};
        const int pb[3] = {1, 2, 2};
        #pragma unroll
        for (int p = 0; p < 3; ++p) {
            bool v = (sel[pa[p]] < NUM_BODY) && (sel[pb[p]] < NUM_BODY);
            sPv[tid][p] = v ? 1.0f : 0.0f;
            sPc[tid][p] = min(sel[pa[p]], NUM_BODY - 1);
            sQc[tid][p] = min(sel[pb[p]], NUM_BODY - 1);
        }
    }
    __syncthreads();

    const int b = blockIdx.x * blockDim.x + tid;
    if (b >= n) return;

    // scalars (L1/const-cached broadcast loads)
    const float base = base_p[0];
    const float p0 = prob[0], p1 = prob[1], p2 = prob[2], p3 = prob[3];
    const float tb = t[b];

    // out[:,0] = log(base) - t*base + log(pi[0])
    out[b * 3 + 0] = logf(base) - tb * base + logf(pi[0]);

    // load this row's data_sample once
    float dsl[NUM_BODY];
    #pragma unroll
    for (int j = 0; j < NUM_BODY; ++j) dsl[j] = ds[b * NUM_BODY + j];

    #pragma unroll
    for (int i = 0; i < NFORM; ++i) {
        // feature dot: empty predicates (cols 30,31) always on
        float dot = sA[i][NUM_BODY] + sA[i][NUM_BODY + 1];
        float mbt = 0.0f;
        #pragma unroll
        for (int j = 0; j < NUM_BODY; ++j) {
            float indj = (dsl[j] <= tb) ? 1.0f : 0.0f;
            float aij  = sA[i][j];
            dot += indj * aij;
            mbt = fmaxf(mbt, indj * dsl[j] * aij);
        }
        float feat = expf(-fabsf(dot - (float)KTOP) / SIGMA);

        // temporal relation feature over 3 pairs
        float wsum = 0.0f, wxsum = 0.0f, pvsum = 0.0f;
        #pragma unroll
        for (int p = 0; p < 3; ++p) {
            float td = dsl[sPc[i][p]] - dsl[sQc[i][p]];
            float c0 = (td >  TOL)        ? 1.0f : 0.0f;
            float c1 = (fabsf(td) < TOL)  ? 1.0f : 0.0f;
            float c2 = (td < -TOL)        ? 1.0f : 0.0f;
            float c3 = 1.0f - p0 * c0 - p1 * c1 - p2 * c2;
            float x0 = c0 * p0, x1 = c1 * p1, x2 = c2 * p2, x3 = c3 * p3;
            float e0 = expf(x0 / TEMP), e1 = expf(x1 / TEMP);
            float e2 = expf(x2 / TEMP), e3 = expf(x3 / TEMP);
            float rrf = (e0 * x0 + e1 * x1 + e2 * x2 + e3 * x3) / (e0 + e1 + e2 + e3);
            float pv = sPv[i][p];
            float w = pv * expf(-rrf / TEMP);
            wsum  += w;
            wxsum += w * rrf;
            pvsum += pv;
        }
        float col = wxsum / fmaxf(wsum, 1e-30f);
        if (!(pvsum > 0.0f)) col = 1.0f;
        feat *= col;

        float sg  = 1.0f / (1.0f + expf(-(tb - mbt)));
        float cur = base + sg * feat * fw[i];
        float lps = logf(cur) + (-tb * cur + sg * (-mbt * base + mbt * cur)) + logf(pi[1 + i]);
        out[b * 3 + 1 + i] = lps;
    }
}

extern "C" void kernel_launch(void* const* d_in, const int* in_sizes, int n_in,
                              void* d_out, int out_size)
{
    const float* t    = (const float*)d_in[0];
    const float* ds   = (const float*)d_in[1];
    const float* pi   = (const float*)d_in[2];
    const float* A    = (const float*)d_in[3];
    const float* base = (const float*)d_in[4];
    const float* fw   = (const float*)d_in[5];
    const float* prob = (const float*)d_in[6];
    float* out = (float*)d_out;

    const int n = in_sizes[0];                 // B = 500 (t has B elements)
    const int threads = 128;
    const int blocks = (n + threads - 1) / threads;
    logic_model_kernel<<<blocks, threads>>>(t, ds, pi, A, base, fw, prob, out, n);
}

// round 2
// speedup vs baseline: 1.1403x; 1.1403x over previous
#include <cuda_runtime.h>
#include <math.h>

#define NUM_BODY 30
#define NPRED    32   // 30 body + 2 empty
#define NFORM    2
#define KTOP     3
#define SIGMA    0.1f
#define TEMP     0.07f
#define TOL      0.02f
#define ROWS_PER_BLK 128
#define DS_PITCH 31   // 31 coprime with 32 banks -> conflict-free row reads

__global__ __launch_bounds__(128)
void logic_model_kernel(const float* __restrict__ t,        // (B,1)
                        const float* __restrict__ ds,       // (B,30)
                        const float* __restrict__ pi,       // (3,)
                        const float* __restrict__ A,        // (2,32)
                        const float* __restrict__ base_p,   // (1,)
                        const float* __restrict__ fw,       // (2,)
                        const float* __restrict__ prob,     // (4,)
                        float* __restrict__ out,            // (B,3)
                        int n)
{
    __shared__ float sA[NFORM][NPRED];
    __shared__ float sPv[NFORM][3];
    __shared__ int   sPc[NFORM][3];
    __shared__ int   sQc[NFORM][3];
    __shared__ float sRrf[4];            // rrf per exclusive case (c0/c1/c2/none)
    __shared__ float sW[4];              // exp(-rrf/TEMP) per case
    __shared__ float sConst[4];          // lp0 = log(base)+log(pi0), lpi1, lpi2, base
    __shared__ float sDS[ROWS_PER_BLK * DS_PITCH];

    const int tid  = threadIdx.x;
    const int lane = tid & 31;
    const int wid  = tid >> 5;

    // ---- stage A (64 floats) ----
    if (tid < NFORM * NPRED) sA[tid / NPRED][tid % NPRED] = A[tid];

    // ---- stage data_sample coalesced into shared ----
    const int rowBase = blockIdx.x * ROWS_PER_BLK;
    const int rows = min(ROWS_PER_BLK, n - rowBase);
    const int total = rows * NUM_BODY;
    for (int k = tid; k < total; k += 128) {
        int r = k / NUM_BODY;
        int c = k - r * NUM_BODY;
        sDS[r * DS_PITCH + c] = ds[rowBase * NUM_BODY + k];
    }

    // ---- per-block scalar precompute (warp 1, lane 0) ----
    if (wid == 1 && lane == 0) {
        float base = base_p[0];
        float p[4] = {prob[0], prob[1], prob[2], prob[3]};
        // 4 exclusive cases: c0=1, c1=1, c2=1, none
        #pragma unroll
        for (int cs = 0; cs < 4; ++cs) {
            float c0 = (cs == 0) ? 1.0f : 0.0f;
            float c1 = (cs == 1) ? 1.0f : 0.0f;
            float c2 = (cs == 2) ? 1.0f : 0.0f;
            float c3 = 1.0f - p[0] * c0 - p[1] * c1 - p[2] * c2;
            float x0 = c0 * p[0], x1 = c1 * p[1], x2 = c2 * p[2], x3 = c3 * p[3];
            float e0 = expf(x0 / TEMP), e1 = expf(x1 / TEMP);
            float e2 = expf(x2 / TEMP), e3 = expf(x3 / TEMP);
            float rrf = (e0 * x0 + e1 * x1 + e2 * x2 + e3 * x3) / (e0 + e1 + e2 + e3);
            sRrf[cs] = rrf;
            sW[cs]   = expf(-rrf / TEMP);
        }
        sConst[0] = logf(base) + logf(pi[0]);
        sConst[1] = logf(pi[1]);
        sConst[2] = logf(pi[2]);
        sConst[3] = base;
    }
    __syncthreads();

    // ---- warp 0: top-3 per formula via shuffle argmax (no local mem) ----
    if (wid == 0) {
        #pragma unroll
        for (int i = 0; i < NFORM; ++i) {
            float v = sA[i][lane];
            int sel0 = 0, sel1 = 0, sel2 = 0;
            #pragma unroll
            for (int k = 0; k < KTOP; ++k) {
                float m = v; int mi = lane;
                #pragma unroll
                for (int off = 16; off > 0; off >>= 1) {
                    float ov = __shfl_down_sync(0xffffffffu, m, off);
                    int   oi = __shfl_down_sync(0xffffffffu, mi, off);
                    if (ov > m || (ov == m && oi < mi)) { m = ov; mi = oi; }
                }
                mi = __shfl_sync(0xffffffffu, mi, 0);
                if (k == 0) sel0 = mi; else if (k == 1) sel1 = mi; else sel2 = mi;
                if (lane == mi) v = -1e30f;
            }
            if (lane == 0) {
                int s[KTOP] = {sel0, sel1, sel2};
                // sort ascending (3 elements)
                if (s[0] > s[1]) { int x = s[0]; s[0] = s[1]; s[1] = x; }
                if (s[1] > s[2]) { int x = s[1]; s[1] = s[2]; s[2] = x; }
                if (s[0] > s[1]) { int x = s[0]; s[0] = s[1]; s[1] = x; }
                const int pa[3] = {0, 0, 1};
                const int pb[3] = {1, 2, 2};
                #pragma unroll
                for (int p = 0; p < 3; ++p) {
                    bool vd = (s[pa[p]] < NUM_BODY) && (s[pb[p]] < NUM_BODY);
                    sPv[i][p] = vd ? 1.0f : 0.0f;
                    sPc[i][p] = min(s[pa[p]], NUM_BODY - 1);
                    sQc[i][p] = min(s[pb[p]], NUM_BODY - 1);
                }
            }
        }
    }
    __syncthreads();

    if (tid >= rows) return;
    const int b = rowBase + tid;

    const float base = sConst[3];
    const float tb   = t[b];
    const float* myds = &sDS[tid * DS_PITCH];

    out[b * 3 + 0] = sConst[0] - tb * base;

    #pragma unroll
    for (int i = 0; i < NFORM; ++i) {
        float dot = sA[i][NUM_BODY] + sA[i][NUM_BODY + 1];
        float mbt = 0.0f;
        #pragma unroll
        for (int j = 0; j < NUM_BODY; ++j) {
            float dv = myds[j];
            float aij = sA[i][j];
            if (dv <= tb) {
                dot += aij;
                mbt = fmaxf(mbt, dv * aij);
            }
        }
        float feat = expf(-fabsf(dot - (float)KTOP) / SIGMA);

        // relation feature via 4-case lookup
        float wsum = 0.0f, wxsum = 0.0f, pvsum = 0.0f;
        #pragma unroll
        for (int p = 0; p < 3; ++p) {
            float td = myds[sPc[i][p]] - myds[sQc[i][p]];
            int cs = 3;
            if (td > TOL) cs = 0;
            else if (fabsf(td) < TOL) cs = 1;
            else if (td < -TOL) cs = 2;
            float rrf = sRrf[cs];
            float pv  = sPv[i][p];
            float w   = pv * sW[cs];
            wsum  += w;
            wxsum += w * rrf;
            pvsum += pv;
        }
        float col = wxsum / fmaxf(wsum, 1e-30f);
        if (!(pvsum > 0.0f)) col = 1.0f;
        feat *= col;

        float sg  = 1.0f / (1.0f + expf(-(tb - mbt)));
        float cur = base + sg * feat * fw[i];
        float lps = logf(cur) + (-tb * cur + sg * (-mbt * base + mbt * cur)) + sConst[1 + i];
        out[b * 3 + 1 + i] = lps;
    }
}

extern "C" void kernel_launch(void* const* d_in, const int* in_sizes, int n_in,
                              void* d_out, int out_size)
{
    const float* t    = (const float*)d_in[0];
    const float* ds   = (const float*)d_in[1];
    const float* pi   = (const float*)d_in[2];
    const float* A    = (const float*)d_in[3];
    const float* base = (const float*)d_in[4];
    const float* fw   = (const float*)d_in[5];
    const float* prob = (const float*)d_in[6];
    float* out = (float*)d_out;

    const int n = in_sizes[0];
    const int threads = 128;
    const int blocks = (n + ROWS_PER_BLK - 1) / ROWS_PER_BLK;
    logic_model_kernel<<<blocks, threads>>>(t, ds, pi, A, base, fw, prob, out, n);
}

// round 3
// speedup vs baseline: 1.7364x; 1.5227x over previous
#include <cuda_runtime.h>
#include <math.h>

#define NUM_BODY 30
#define NPRED    32
#define NFORM    2
#define KTOP     3
#define SIGMA    0.1f
#define TEMP     0.07f
#define TOL      0.02f

// rrf for one exclusive case: exactly one active indicator with value xa
// (xa==0 encodes the "none" case), plus the residual x3 term.
// rrf = (e_a*xa + e3*x3) / (e_a + 2 + e3)  with e_a=exp(xa/T), e3=exp(x3/T)
__device__ __forceinline__ float case_rrf(float xa, float x3) {
    float ea = expf(xa * (1.0f / TEMP));
    float e3 = expf(x3 * (1.0f / TEMP));
    return fmaf(ea, xa, e3 * x3) / (ea + 2.0f + e3);
}

__global__ __launch_bounds__(32)
void logic_model_kernel(const float* __restrict__ t,        // (B,1)
                        const float* __restrict__ ds,       // (B,30)
                        const float* __restrict__ pi,       // (3,)
                        const float* __restrict__ A,        // (2,32)
                        const float* __restrict__ base_p,   // (1,)
                        const float* __restrict__ fw,       // (2,)
                        const float* __restrict__ prob,     // (4,)
                        float* __restrict__ out,            // (B,3)
                        int n)
{
    const int lane = threadIdx.x;
    const int b    = blockIdx.x * 32 + lane;
    const int bc   = min(b, n - 1);          // clamped row for loads
    const bool act = (b < n);

    // ---- issue all global loads early (independent of shuffle chain) ----
    const float tb = t[bc];
    float dsl[NUM_BODY];
    #pragma unroll
    for (int j = 0; j < NUM_BODY; ++j) dsl[j] = ds[bc * NUM_BODY + j];

    const float base = base_p[0];
    const float p0 = prob[0], p1 = prob[1], p2 = prob[2], p3 = prob[3];
    const float fw0 = fw[0], fw1 = fw[1];
    const float lpi0 = logf(pi[0]), lpi1 = logf(pi[1]), lpi2 = logf(pi[2]);

    // A staged per-lane: a0/a1 = A[formula][lane]
    float aval[NFORM];
    aval[0] = A[lane];
    aval[1] = A[NPRED + lane];

    // ---- per-thread 4-case rrf / weight table (registers) ----
    float rrfT[4], wT[4];
    {
        // case cs<3: active indicator value p[cs], c3 = 1-p[cs]; case 3: xa=0, c3=1
        rrfT[0] = case_rrf(p0, (1.0f - p0) * p3);
        rrfT[1] = case_rrf(p1, (1.0f - p1) * p3);
        rrfT[2] = case_rrf(p2, (1.0f - p2) * p3);
        rrfT[3] = case_rrf(0.0f, p3);
        #pragma unroll
        for (int cs = 0; cs < 4; ++cs) wT[cs] = expf(-rrfT[cs] * (1.0f / TEMP));
    }

    // ---- warp-parallel top-3 per formula (butterfly: all lanes get result) ----
    float pvF[NFORM][3];
    int   pcF[NFORM][3], qcF[NFORM][3];
    #pragma unroll
    for (int i = 0; i < NFORM; ++i) {
        float v = aval[i];
        int s[KTOP];
        #pragma unroll
        for (int k = 0; k < KTOP; ++k) {
            float m = v; int mi = lane;
            #pragma unroll
            for (int off = 16; off > 0; off >>= 1) {
                float ov = __shfl_xor_sync(0xffffffffu, m, off);
                int   oi = __shfl_xor_sync(0xffffffffu, mi, off);
                if (ov > m || (ov == m && oi < mi)) { m = ov; mi = oi; }
            }
            s[k] = mi;
            if (lane == mi) v = -1e30f;
        }
        // sort ascending (3 elems)
        if (s[0] > s[1]) { int x = s[0]; s[0] = s[1]; s[1] = x; }
        if (s[1] > s[2]) { int x = s[1]; s[1] = s[2]; s[2] = x; }
        if (s[0] > s[1]) { int x = s[0]; s[0] = s[1]; s[1] = x; }
        const int pa[3] = {0, 0, 1};
        const int pb[3] = {1, 2, 2};
        #pragma unroll
        for (int p = 0; p < 3; ++p) {
            bool vd = (s[pa[p]] < NUM_BODY) && (s[pb[p]] < NUM_BODY);
            pvF[i][p] = vd ? 1.0f : 0.0f;
            pcF[i][p] = min(s[pa[p]], NUM_BODY - 1);
            qcF[i][p] = min(s[pb[p]], NUM_BODY - 1);
        }
    }

    // broadcast A row values needed per formula via shuffle-free reload:
    // (A lines are L1-resident; scalar reads below are broadcast L1 hits)

    if (act) out[b * 3 + 0] = logf(base) - tb * base + lpi0;

    #pragma unroll
    for (int i = 0; i < NFORM; ++i) {
        // dot & max-body-time over the 30 body predicates
        float dot = A[i * NPRED + NUM_BODY] + A[i * NPRED + NUM_BODY + 1];
        float mbt = 0.0f;
        #pragma unroll
        for (int j = 0; j < NUM_BODY; ++j) {
            float dv  = dsl[j];
            float aij = A[i * NPRED + j];   // broadcast, L1 hit
            if (dv <= tb) {
                dot += aij;
                mbt = fmaxf(mbt, dv * aij);
            }
        }
        float feat = expf(-fabsf(dot - (float)KTOP) * (1.0f / SIGMA));

        float wsum = 0.0f, wxsum = 0.0f, pvsum = 0.0f;
        #pragma unroll
        for (int p = 0; p < 3; ++p) {
            // L1-hit scalar loads avoid dynamic register indexing (no local mem)
            float td = ds[bc * NUM_BODY + pcF[i][p]] - ds[bc * NUM_BODY + qcF[i][p]];
            int cs = 3;
            if (td > TOL) cs = 0;
            else if (fabsf(td) < TOL) cs = 1;
            else if (td < -TOL) cs = 2;
            float pv = pvF[i][p];
            float w  = pv * wT[cs];
            wsum  += w;
            wxsum += w * rrfT[cs];
            pvsum += pv;
        }
        float col = wxsum / fmaxf(wsum, 1e-30f);
        if (!(pvsum > 0.0f)) col = 1.0f;
        feat *= col;

        float sg  = 1.0f / (1.0f + expf(-(tb - mbt)));
        float cur = fmaf(sg * feat, (i == 0 ? fw0 : fw1), base);
        float lps = logf(cur) + (-tb * cur + sg * (-mbt * base + mbt * cur))
                  + (i == 0 ? lpi1 : lpi2);
        if (act) out[b * 3 + 1 + i] = lps;
    }
}

extern "C" void kernel_launch(void* const* d_in, const int* in_sizes, int n_in,
                              void* d_out, int out_size)
{
    const float* t    = (const float*)d_in[0];
    const float* ds   = (const float*)d_in[1];
    const float* pi   = (const float*)d_in[2];
    const float* A    = (const float*)d_in[3];
    const float* base = (const float*)d_in[4];
    const float* fw   = (const float*)d_in[5];
    const float* prob = (const float*)d_in[6];
    float* out = (float*)d_out;

    const int n = in_sizes[0];
    const int blocks = (n + 31) / 32;     // 16 blocks of 1 warp
    logic_model_kernel<<<blocks, 32>>>(t, ds, pi, A, base, fw, prob, out, n);
}

// round 4
// speedup vs baseline: 1.7685x; 1.0185x over previous
#include <cuda_runtime.h>
#include <math.h>

#define NUM_BODY 30
#define NPRED    32
#define NFORM    2
#define KTOP     3
#define SIGMA    0.1f
#define TEMP     0.07f
#define TOL      0.02f

// rrf for one exclusive case: exactly one active indicator with value xa
// (xa==0 encodes the "none" case), plus residual x3.
__device__ __forceinline__ float case_rrf(float xa, float x3) {
    float ea = expf(xa * (1.0f / TEMP));
    float e3 = expf(x3 * (1.0f / TEMP));
    return fmaf(ea, xa, e3 * x3) / (ea + 2.0f + e3);
}

__global__ __launch_bounds__(32)
void logic_model_kernel(const float* __restrict__ t,        // (B,1)
                        const float* __restrict__ ds,       // (B,30)
                        const float* __restrict__ pi,       // (3,)
                        const float* __restrict__ A,        // (2,32)
                        const float* __restrict__ base_p,   // (1,)
                        const float* __restrict__ fw,       // (2,)
                        const float* __restrict__ prob,     // (4,)
                        float* __restrict__ out,            // (B,3)
                        int n)
{
    const int lane = threadIdx.x;
    const int f    = blockIdx.x & 1;           // formula handled by this block
    const int b    = (blockIdx.x >> 1) * 32 + lane;
    const int bc   = min(b, n - 1);
    const bool act = (b < n);

    // ---- issue global loads as early as possible ----
    const float tb = t[bc];
    // ds row: 120 bytes, always 8B aligned -> 15x LDG.64
    float dsl[NUM_BODY];
    {
        const float2* ds2 = (const float2*)(ds + bc * NUM_BODY);
        #pragma unroll
        for (int j = 0; j < NUM_BODY / 2; ++j) {
            float2 v = ds2[j];
            dsl[2 * j]     = v.x;
            dsl[2 * j + 1] = v.y;
        }
    }
    const float aval = A[f * NPRED + lane];    // per-lane A value for topk

    const float base = base_p[0];
    const float p0 = prob[0], p1 = prob[1], p2 = prob[2], p3 = prob[3];
    const float fwf  = fw[f];
    const float lpi0 = logf(pi[0]);
    const float lpif = logf(pi[1 + f]);

    // ---- per-thread 4-case rrf / weight table ----
    float rrfT[4], wT[4];
    rrfT[0] = case_rrf(p0, (1.0f - p0) * p3);
    rrfT[1] = case_rrf(p1, (1.0f - p1) * p3);
    rrfT[2] = case_rrf(p2, (1.0f - p2) * p3);
    rrfT[3] = case_rrf(0.0f, p3);
    #pragma unroll
    for (int cs = 0; cs < 4; ++cs) wT[cs] = expf(-rrfT[cs] * (1.0f / TEMP));

    // ---- warp-parallel top-3 for this formula (butterfly argmax x3) ----
    // Overlaps with the in-flight ds DRAM loads.
    float pv3[3];
    int   pc3[3], qc3[3];
    {
        float v = aval;
        int s[KTOP];
        #pragma unroll
        for (int k = 0; k < KTOP; ++k) {
            float m = v; int mi = lane;
            #pragma unroll
            for (int off = 16; off > 0; off >>= 1) {
                float ov = __shfl_xor_sync(0xffffffffu, m, off);
                int   oi = __shfl_xor_sync(0xffffffffu, mi, off);
                if (ov > m || (ov == m && oi < mi)) { m = ov; mi = oi; }
            }
            s[k] = mi;
            if (lane == mi) v = -1e30f;
        }
        if (s[0] > s[1]) { int x = s[0]; s[0] = s[1]; s[1] = x; }
        if (s[1] > s[2]) { int x = s[1]; s[1] = s[2]; s[2] = x; }
        if (s[0] > s[1]) { int x = s[0]; s[0] = s[1]; s[1] = x; }
        const int pa[3] = {0, 0, 1};
        const int pb[3] = {1, 2, 2};
        #pragma unroll
        for (int p = 0; p < 3; ++p) {
            bool vd = (s[pa[p]] < NUM_BODY) && (s[pb[p]] < NUM_BODY);
            pv3[p] = vd ? 1.0f : 0.0f;
            pc3[p] = min(s[pa[p]], NUM_BODY - 1);
            qc3[p] = min(s[pb[p]], NUM_BODY - 1);
        }
    }

    if (f == 0 && act) out[b * 3 + 0] = logf(base) - tb * base + lpi0;

    // ---- formula body: 4-way partial dot + fmax tree ----
    const float* Af = A + f * NPRED;
    float dotP[4] = {Af[NUM_BODY], Af[NUM_BODY + 1], 0.0f, 0.0f};
    float mbtP[4] = {0.0f, 0.0f, 0.0f, 0.0f};
    #pragma unroll
    for (int j = 0; j < NUM_BODY; ++j) {
        float dv  = dsl[j];
        float aij = Af[j];                 // broadcast L1 hit
        int q = j & 3;
        if (dv <= tb) {
            dotP[q] += aij;
            mbtP[q] = fmaxf(mbtP[q], dv * aij);
        }
    }
    float dot = (dotP[0] + dotP[1]) + (dotP[2] + dotP[3]);
    float mbt = fmaxf(fmaxf(mbtP[0], mbtP[1]), fmaxf(mbtP[2], mbtP[3]));

    float feat = expf(-fabsf(dot - (float)KTOP) * (1.0f / SIGMA));

    float wsum = 0.0f, wxsum = 0.0f, pvsum = 0.0f;
    #pragma unroll
    for (int p = 0; p < 3; ++p) {
        // L1-hit scalar loads (lines already resident from the row load)
        float td = ds[bc * NUM_BODY + pc3[p]] - ds[bc * NUM_BODY + qc3[p]];
        int cs = 3;
        if (td > TOL) cs = 0;
        else if (fabsf(td) < TOL) cs = 1;
        else if (td < -TOL) cs = 2;
        float pv = pv3[p];
        float w  = pv * wT[cs];
        wsum  += w;
        wxsum += w * rrfT[cs];
        pvsum += pv;
    }
    float col = wxsum / fmaxf(wsum, 1e-30f);
    if (!(pvsum > 0.0f)) col = 1.0f;
    feat *= col;

    float sg  = 1.0f / (1.0f + expf(-(tb - mbt)));
    float cur = fmaf(sg * feat, fwf, base);
    float lps = logf(cur) + (-tb * cur + sg * (-mbt * base + mbt * cur)) + lpif;
    if (act) out[b * 3 + 1 + f] = lps;
}

extern "C" void kernel_launch(void* const* d_in, const int* in_sizes, int n_in,
                              void* d_out, int out_size)
{
    const float* t    = (const float*)d_in[0];
    const float* ds   = (const float*)d_in[1];
    const float* pi   = (const float*)d_in[2];
    const float* A    = (const float*)d_in[3];
    const float* base = (const float*)d_in[4];
    const float* fw   = (const float*)d_in[5];
    const float* prob = (const float*)d_in[6];
    float* out = (float*)d_out;

    const int n = in_sizes[0];
    const int rowblks = (n + 31) / 32;        // 16 for B=500
    const int blocks  = rowblks * NFORM;      // 32 blocks: (row-group, formula)
    logic_model_kernel<<<blocks, 32>>>(t, ds, pi, A, base, fw, prob, out, n);
}

// round 5
// speedup vs baseline: 1.8454x; 1.0435x over previous
#include <cuda_runtime.h>
#include <math.h>

#define NUM_BODY 30
#define NPRED    32
#define NFORM    2
#define KTOP     3
#define SIGMA    0.1f
#define TEMP     0.07f
#define TOL      0.02f

__device__ __forceinline__ float case_rrf(float xa, float x3) {
    float ea = expf(xa * (1.0f / TEMP));
    float e3 = expf(x3 * (1.0f / TEMP));
    return fmaf(ea, xa, e3 * x3) / (ea + 2.0f + e3);
}

__global__ __launch_bounds__(32)
void logic_model_kernel(const float* __restrict__ t,        // (B,1)
                        const float* __restrict__ ds,       // (B,30)
                        const float* __restrict__ pi,       // (3,)
                        const float* __restrict__ A,        // (2,32)
                        const float* __restrict__ base_p,   // (1,)
                        const float* __restrict__ fw,       // (2,)
                        const float* __restrict__ prob,     // (4,)
                        float* __restrict__ out,            // (B,3)
                        int n)
{
    const int lane = threadIdx.x;
    const int f    = blockIdx.x & 1;
    const int b    = (blockIdx.x >> 1) * 32 + lane;
    const int bc   = min(b, n - 1);
    const bool act = (b < n);

    // ---- issue ALL global loads up front (max MLP, one latency exposure) ----
    const float tb = t[bc];
    float dsl[NUM_BODY];
    {
        const float2* ds2 = (const float2*)(ds + bc * NUM_BODY);
        #pragma unroll
        for (int j = 0; j < NUM_BODY / 2; ++j) {
            float2 v = ds2[j];
            dsl[2 * j]     = v.x;
            dsl[2 * j + 1] = v.y;
        }
    }
    // full A row for this formula: 32 floats = 2x LDG.128 per lane (broadcast)
    float av[NPRED];
    {
        const float4* A4 = (const float4*)(A + f * NPRED);
        #pragma unroll
        for (int q = 0; q < NPRED / 4; ++q) {
            float4 v = A4[q];
            av[4 * q]     = v.x;
            av[4 * q + 1] = v.y;
            av[4 * q + 2] = v.z;
            av[4 * q + 3] = v.w;
        }
    }
    const float base = base_p[0];
    const float p0 = prob[0], p1 = prob[1], p2 = prob[2], p3 = prob[3];
    const float fwf  = fw[f];
    const float lpi0 = logf(pi[0]);
    const float lpif = logf(pi[1 + f]);

    // ---- 4-case rrf / weight table (independent MUFU work, overlaps loads) ----
    float rrfT[4], wT[4];
    rrfT[0] = case_rrf(p0, (1.0f - p0) * p3);
    rrfT[1] = case_rrf(p1, (1.0f - p1) * p3);
    rrfT[2] = case_rrf(p2, (1.0f - p2) * p3);
    rrfT[3] = case_rrf(0.0f, p3);
    #pragma unroll
    for (int cs = 0; cs < 4; ++cs) wT[cs] = expf(-rrfT[cs] * (1.0f / TEMP));

    // ---- top-3 via rank-by-comparison + single ballot ----
    // rank(lane) = #{k: A[k] > A[lane]} + #{k: A[k] == A[lane], k < lane}
    // top-3 = lanes with rank < 3; ballot bits give indices in ascending order,
    // matching jax.lax.top_k (desc value, low-index tie-break) + jnp.sort.
    int s0, s1, s2;
    {
        const float mine = av[lane];
        int rank = 0;
        #pragma unroll
        for (int k = 0; k < NPRED; ++k) {
            float vk = av[k];
            rank += (vk > mine || (vk == mine && k < lane)) ? 1 : 0;
        }
        unsigned m = __ballot_sync(0xffffffffu, rank < KTOP);
        s0 = __ffs(m) - 1;  m &= m - 1;
        s1 = __ffs(m) - 1;  m &= m - 1;
        s2 = __ffs(m) - 1;
    }
    const int sel[KTOP] = {s0, s1, s2};
    float pv3[3]; int pc3[3], qc3[3];
    {
        const int pa[3] = {0, 0, 1};
        const int pb[3] = {1, 2, 2};
        #pragma unroll
        for (int p = 0; p < 3; ++p) {
            bool vd = (sel[pa[p]] < NUM_BODY) && (sel[pb[p]] < NUM_BODY);
            pv3[p] = vd ? 1.0f : 0.0f;
            pc3[p] = min(sel[pa[p]], NUM_BODY - 1);
            qc3[p] = min(sel[pb[p]], NUM_BODY - 1);
        }
    }

    if (f == 0 && act) out[b * 3 + 0] = logf(base) - tb * base + lpi0;

    // ---- formula body: 4-way partial dot + fmax tree ----
    float dotP[4] = {av[NUM_BODY], av[NUM_BODY + 1], 0.0f, 0.0f};
    float mbtP[4] = {0.0f, 0.0f, 0.0f, 0.0f};
    #pragma unroll
    for (int j = 0; j < NUM_BODY; ++j) {
        float dv  = dsl[j];
        float aij = av[j];
        int q = j & 3;
        if (dv <= tb) {
            dotP[q] += aij;
            mbtP[q] = fmaxf(mbtP[q], dv * aij);
        }
    }
    float dot = (dotP[0] + dotP[1]) + (dotP[2] + dotP[3]);
    float mbt = fmaxf(fmaxf(mbtP[0], mbtP[1]), fmaxf(mbtP[2], mbtP[3]));

    float feat = expf(-fabsf(dot - (float)KTOP) * (1.0f / SIGMA));

    float wsum = 0.0f, wxsum = 0.0f, pvsum = 0.0f;
    #pragma unroll
    for (int p = 0; p < 3; ++p) {
        // L1-hit scalar loads (lines resident from the vectorized row load)
        float td = ds[bc * NUM_BODY + pc3[p]] - ds[bc * NUM_BODY + qc3[p]];
        int cs = 3;
        if (td > TOL) cs = 0;
        else if (fabsf(td) < TOL) cs = 1;
        else if (td < -TOL) cs = 2;
        float pv = pv3[p];
        float w  = pv * wT[cs];
        wsum  += w;
        wxsum += w * rrfT[cs];
        pvsum += pv;
    }
    float col = wxsum / fmaxf(wsum, 1e-30f);
    if (!(pvsum > 0.0f)) col = 1.0f;
    feat *= col;

    float sg  = 1.0f / (1.0f + expf(-(tb - mbt)));
    float cur = fmaf(sg * feat, fwf, base);
    float lps = logf(cur) + (-tb * cur + sg * (-mbt * base + mbt * cur)) + lpif;
    if (act) out[b * 3 + 1 + f] = lps;
}

extern "C" void kernel_launch(void* const* d_in, const int* in_sizes, int n_in,
                              void* d_out, int out_size)
{
    const float* t    = (const float*)d_in[0];
    const float* ds   = (const float*)d_in[1];
    const float* pi   = (const float*)d_in[2];
    const float* A    = (const float*)d_in[3];
    const float* base = (const float*)d_in[4];
    const float* fw   = (const float*)d_in[5];
    const float* prob = (const float*)d_in[6];
    float* out = (float*)d_out;

    const int n = in_sizes[0];
    const int rowblks = (n + 31) / 32;
    const int blocks  = rowblks * NFORM;
    logic_model_kernel<<<blocks, 32>>>(t, ds, pi, A, base, fw, prob, out, n);
}